// round 1
// baseline (speedup 1.0000x reference)
#include <cuda_runtime.h>
#include <cuda_fp16.h>

// Sinkhorn: B=128, N=M=1024, 10 iterations, eps=0.05, stab=1e-8.
// Strategy: memory-bound problem.
//   1) prep: K16 = fp16(exp(-20*C))           (read 512MB, write 256MB)
//   2) 10x fused iteration: one pass over K16 computes u = 1/(K v + e)
//      AND column partials for v (K tile stays in registers).   (256MB/iter)
//      + tiny combine kernel: v = 1/(sum partials + e)
//   3) final: out = u * exp(-20*C) * v  (fp32 K recomputed)  (read 512 + write 512MB)

#define Bb   128
#define Nn   1024
#define Mm   1024
#define CHUNKS 16                      // row chunks per batch
#define ROWS_PER_BLK (Nn / CHUNKS)     // 64
#define EPS_STAB 1e-8f
#define NEG_INV_EPS (-20.0f)           // -1/0.05

static const size_t TOT = (size_t)Bb * Nn * Mm;   // 134217728

__device__ __half g_K[(size_t)Bb * Nn * Mm];      // 256 MB scratch
__device__ float  g_u[Bb * Nn];
__device__ float  g_v[Bb * Mm];
__device__ float  g_vp[CHUNKS][Bb * Mm];          // per-chunk column partials

// ---------------------------------------------------------------- init v
__global__ void k_init_v() {
    int i = blockIdx.x * blockDim.x + threadIdx.x;
    if (i < Bb * Mm) g_v[i] = 1.0f / (float)Mm;
}

// ---------------------------------------------------------------- prep: K16
__global__ void k_prep(const float* __restrict__ C) {
    size_t i = (size_t)blockIdx.x * blockDim.x + threadIdx.x;
    size_t stride = (size_t)gridDim.x * blockDim.x;
    const float4* C4 = reinterpret_cast<const float4*>(C);
    uint2* K2 = reinterpret_cast<uint2*>(g_K);
    size_t n4 = TOT / 4;
    for (; i < n4; i += stride) {
        float4 c = C4[i];
        __half2 h0 = __floats2half2_rn(__expf(NEG_INV_EPS * c.x),
                                       __expf(NEG_INV_EPS * c.y));
        __half2 h1 = __floats2half2_rn(__expf(NEG_INV_EPS * c.z),
                                       __expf(NEG_INV_EPS * c.w));
        uint2 pk;
        pk.x = *reinterpret_cast<unsigned*>(&h0);
        pk.y = *reinterpret_cast<unsigned*>(&h1);
        K2[i] = pk;
    }
}

// ---------------------------------------------------------------- fused iter
// Block: 128 threads, handles (batch b, 64-row chunk c).
// Thread t owns columns [8t, 8t+8). Per 4-row group:
//   load 4x16B of K (8 halves each), convert once, dot with v (registers),
//   block-reduce -> u for those rows, then reuse the SAME register K values
//   to accumulate column partials vacc += K^T u.
__device__ __forceinline__ void cvt8(uint4 q, float* k) {
    __half2 h;
    float2 f;
    h = *reinterpret_cast<__half2*>(&q.x); f = __half22float2(h); k[0] = f.x; k[1] = f.y;
    h = *reinterpret_cast<__half2*>(&q.y); f = __half22float2(h); k[2] = f.x; k[3] = f.y;
    h = *reinterpret_cast<__half2*>(&q.z); f = __half22float2(h); k[4] = f.x; k[5] = f.y;
    h = *reinterpret_cast<__half2*>(&q.w); f = __half22float2(h); k[6] = f.x; k[7] = f.y;
}

__global__ void __launch_bounds__(128) k_iter() {
    const int t    = threadIdx.x;        // 0..127
    const int c    = blockIdx.x;         // 0..CHUNKS-1
    const int b    = blockIdx.y;         // 0..127
    const int lane = t & 31;
    const int warp = t >> 5;
    const int m0   = t * 8;

    // v columns owned by this thread (fp32, registers)
    float v[8];
    {
        const float4* vg = reinterpret_cast<const float4*>(g_v + b * Mm + m0);
        float4 va = vg[0], vb = vg[1];
        v[0] = va.x; v[1] = va.y; v[2] = va.z; v[3] = va.w;
        v[4] = vb.x; v[5] = vb.y; v[6] = vb.z; v[7] = vb.w;
    }

    float vacc[8];
#pragma unroll
    for (int j = 0; j < 8; j++) vacc[j] = 0.0f;

    __shared__ float4 ws[2][4];          // double-buffered per-warp row sums

    const __half* Kbase = g_K + ((size_t)b * Nn + c * ROWS_PER_BLK) * Mm;
    const int n_base = b * Nn + c * ROWS_PER_BLK;

    for (int g = 0; g < ROWS_PER_BLK / 4; ++g) {
        const uint4* Kr = reinterpret_cast<const uint4*>(
            Kbase + (size_t)(g * 4) * Mm + m0);
        // 4 independent row loads (row stride = 1024 halves = 128 uint4)
        uint4 q0 = Kr[0];
        uint4 q1 = Kr[128];
        uint4 q2 = Kr[256];
        uint4 q3 = Kr[384];

        float k0[8], k1[8], k2[8], k3[8];
        cvt8(q0, k0); cvt8(q1, k1); cvt8(q2, k2); cvt8(q3, k3);

        float p0 = 0.f, p1 = 0.f, p2 = 0.f, p3 = 0.f;
#pragma unroll
        for (int j = 0; j < 8; j++) {
            p0 = fmaf(k0[j], v[j], p0);
            p1 = fmaf(k1[j], v[j], p1);
            p2 = fmaf(k2[j], v[j], p2);
            p3 = fmaf(k3[j], v[j], p3);
        }
#pragma unroll
        for (int off = 16; off; off >>= 1) {
            p0 += __shfl_xor_sync(0xffffffffu, p0, off);
            p1 += __shfl_xor_sync(0xffffffffu, p1, off);
            p2 += __shfl_xor_sync(0xffffffffu, p2, off);
            p3 += __shfl_xor_sync(0xffffffffu, p3, off);
        }
        const int buf = g & 1;
        if (lane == 0) ws[buf][warp] = make_float4(p0, p1, p2, p3);
        __syncthreads();
        float4 s0 = ws[buf][0], s1 = ws[buf][1], s2 = ws[buf][2], s3 = ws[buf][3];
        float sx = (s0.x + s1.x) + (s2.x + s3.x);
        float sy = (s0.y + s1.y) + (s2.y + s3.y);
        float sz = (s0.z + s1.z) + (s2.z + s3.z);
        float sw = (s0.w + s1.w) + (s2.w + s3.w);
        float u0 = __fdividef(1.0f, sx + EPS_STAB);
        float u1 = __fdividef(1.0f, sy + EPS_STAB);
        float u2 = __fdividef(1.0f, sz + EPS_STAB);
        float u3 = __fdividef(1.0f, sw + EPS_STAB);

        if (t == 0) g_u[n_base + g * 4 + 0] = u0;
        if (t == 1) g_u[n_base + g * 4 + 1] = u1;
        if (t == 2) g_u[n_base + g * 4 + 2] = u2;
        if (t == 3) g_u[n_base + g * 4 + 3] = u3;

#pragma unroll
        for (int j = 0; j < 8; j++) {
            vacc[j] = fmaf(k0[j], u0, vacc[j]);
            vacc[j] = fmaf(k1[j], u1, vacc[j]);
            vacc[j] = fmaf(k2[j], u2, vacc[j]);
            vacc[j] = fmaf(k3[j], u3, vacc[j]);
        }
    }

    float4* vp = reinterpret_cast<float4*>(g_vp[c] + b * Mm + m0);
    vp[0] = make_float4(vacc[0], vacc[1], vacc[2], vacc[3]);
    vp[1] = make_float4(vacc[4], vacc[5], vacc[6], vacc[7]);
}

// ---------------------------------------------------------------- combine v
__global__ void k_comb() {
    int i = blockIdx.x * blockDim.x + threadIdx.x;   // 131072 total
    float s = 0.f;
#pragma unroll
    for (int c = 0; c < CHUNKS; c++) s += g_vp[c][i];
    g_v[i] = __fdividef(1.0f, s + EPS_STAB);
}

// ---------------------------------------------------------------- final out
__global__ void __launch_bounds__(256) k_final(const float* __restrict__ C,
                                               float* __restrict__ out) {
    int row = blockIdx.x;               // b*1024 + n, 0..131071
    int t   = threadIdx.x;              // 0..255 (4 cols each)
    int b   = row >> 10;
    float u = g_u[row];
    float4 v4 = reinterpret_cast<const float4*>(g_v)[b * (Mm / 4) + t];
    size_t off = (size_t)row * (Mm / 4) + t;
    float4 c = reinterpret_cast<const float4*>(C)[off];
    float4 o;
    o.x = u * __expf(NEG_INV_EPS * c.x) * v4.x;
    o.y = u * __expf(NEG_INV_EPS * c.y) * v4.y;
    o.z = u * __expf(NEG_INV_EPS * c.z) * v4.z;
    o.w = u * __expf(NEG_INV_EPS * c.w) * v4.w;
    reinterpret_cast<float4*>(out)[off] = o;
}

// ---------------------------------------------------------------- launch
extern "C" void kernel_launch(void* const* d_in, const int* in_sizes, int n_in,
                              void* d_out, int out_size) {
    const float* C = (const float*)d_in[0];
    float* out = (float*)d_out;

    k_init_v<<<(Bb * Mm + 255) / 256, 256>>>();
    k_prep<<<1184, 256>>>(C);

    for (int it = 0; it < 10; ++it) {
        k_iter<<<dim3(CHUNKS, Bb), 128>>>();
        k_comb<<<(Bb * Mm + 255) / 256, 256>>>();
    }

    k_final<<<Bb * Nn, 256>>>(C, out);
}

// round 2
// speedup vs baseline: 1.0914x; 1.0914x over previous
#include <cuda_runtime.h>
#include <cuda_fp16.h>

// Sinkhorn: B=128, N=M=1024, 10 iters, eps=0.05, stab=1e-8. Memory-bound.
//   iter0 (FIRST): reads C fp32, K=exp(-20C) on the fly, writes K16, does
//                  fused u/v-partial pass with v=1/M.
//   iters 1..9:    one pass over K16 per iteration. Each warp owns 64 rows x
//                  all 1024 cols; u via shfl reduce (no block barriers);
//                  column partials combined in smem once at block end.
//                  v is reconstructed from previous iteration's 4 per-chunk
//                  partials in the prologue (double-buffered -> no race).
//   k_comb (once): final v from last partials.
//   k_final:       out = u * K16 * v (v cached in smem, 32 rows/block).

#define Bb   128
#define Nn   1024
#define Mm   1024
#define CHUNKS 4                         // row chunks (blocks) per batch
#define WARPS_PER_BLK 4
#define ROWS_PER_WARP 64
#define EPS_STAB 1e-8f
#define NEG_INV_EPS (-20.0f)

__device__ __half g_K[(size_t)Bb * Nn * Mm];        // 256 MB
__device__ float  g_u[Bb * Nn];
__device__ float  g_v[Bb * Mm];
__device__ float  g_vp[2][CHUNKS][Bb * Mm];         // double-buffered partials

__device__ __forceinline__ void cvt8(uint4 q, float* k) {
    __half2 h; float2 f;
    h = *reinterpret_cast<__half2*>(&q.x); f = __half22float2(h); k[0]=f.x; k[1]=f.y;
    h = *reinterpret_cast<__half2*>(&q.y); f = __half22float2(h); k[2]=f.x; k[3]=f.y;
    h = *reinterpret_cast<__half2*>(&q.z); f = __half22float2(h); k[4]=f.x; k[5]=f.y;
    h = *reinterpret_cast<__half2*>(&q.w); f = __half22float2(h); k[6]=f.x; k[7]=f.y;
}

__device__ __forceinline__ float warp_sum(float p) {
#pragma unroll
    for (int o = 16; o; o >>= 1) p += __shfl_xor_sync(0xffffffffu, p, o);
    return p;
}

// ---------------------------------------------------------------- fused iter
// grid (CHUNKS, Bb), 128 threads. Warp w handles rows [c*256+w*64, +64).
// Thread (w,l) owns columns { j*256 + l*8 + e : j=0..3, e=0..7 }.
template<bool FIRST>
__global__ void __launch_bounds__(128) k_iter(const float* __restrict__ C, int par) {
    const int l = threadIdx.x & 31;
    const int w = threadIdx.x >> 5;
    const int c = blockIdx.x;
    const int b = blockIdx.y;
    const int row0  = c * (WARPS_PER_BLK * ROWS_PER_WARP) + w * ROWS_PER_WARP;
    const int nbase = b * Nn + row0;

    float v[32], vacc[32];
#pragma unroll
    for (int i = 0; i < 32; i++) vacc[i] = 0.0f;

    if (FIRST) {
#pragma unroll
        for (int i = 0; i < 32; i++) v[i] = 1.0f / (float)Mm;
    } else {
        const int pp = par ^ 1;
#pragma unroll
        for (int j = 0; j < 4; j++) {
#pragma unroll
            for (int h = 0; h < 2; h++) {
                const int col = j * 256 + l * 8 + h * 4;
                float4 s = *reinterpret_cast<const float4*>(&g_vp[pp][0][b * Mm + col]);
#pragma unroll
                for (int c2 = 1; c2 < CHUNKS; c2++) {
                    float4 t = *reinterpret_cast<const float4*>(&g_vp[pp][c2][b * Mm + col]);
                    s.x += t.x; s.y += t.y; s.z += t.z; s.w += t.w;
                }
                v[j*8 + h*4 + 0] = __fdividef(1.0f, s.x + EPS_STAB);
                v[j*8 + h*4 + 1] = __fdividef(1.0f, s.y + EPS_STAB);
                v[j*8 + h*4 + 2] = __fdividef(1.0f, s.z + EPS_STAB);
                v[j*8 + h*4 + 3] = __fdividef(1.0f, s.w + EPS_STAB);
            }
        }
    }

    if (FIRST) {
        const float4* Cp = reinterpret_cast<const float4*>(C + (size_t)nbase * Mm);
        uint4* Kw = reinterpret_cast<uint4*>(g_K + (size_t)nbase * Mm);
        for (int r = 0; r < ROWS_PER_WARP; ++r) {
            float k[32];
#pragma unroll
            for (int j = 0; j < 4; j++) {
                float4 a = Cp[r*256 + j*64 + l*2];
                float4 q = Cp[r*256 + j*64 + l*2 + 1];
                k[j*8+0] = __expf(NEG_INV_EPS * a.x);
                k[j*8+1] = __expf(NEG_INV_EPS * a.y);
                k[j*8+2] = __expf(NEG_INV_EPS * a.z);
                k[j*8+3] = __expf(NEG_INV_EPS * a.w);
                k[j*8+4] = __expf(NEG_INV_EPS * q.x);
                k[j*8+5] = __expf(NEG_INV_EPS * q.y);
                k[j*8+6] = __expf(NEG_INV_EPS * q.z);
                k[j*8+7] = __expf(NEG_INV_EPS * q.w);
            }
            // store K16
#pragma unroll
            for (int j = 0; j < 4; j++) {
                __half2 h0 = __floats2half2_rn(k[j*8+0], k[j*8+1]);
                __half2 h1 = __floats2half2_rn(k[j*8+2], k[j*8+3]);
                __half2 h2 = __floats2half2_rn(k[j*8+4], k[j*8+5]);
                __half2 h3 = __floats2half2_rn(k[j*8+6], k[j*8+7]);
                uint4 pk;
                pk.x = *reinterpret_cast<unsigned*>(&h0);
                pk.y = *reinterpret_cast<unsigned*>(&h1);
                pk.z = *reinterpret_cast<unsigned*>(&h2);
                pk.w = *reinterpret_cast<unsigned*>(&h3);
                Kw[r*128 + j*32 + l] = pk;
            }
            float p = 0.0f;
#pragma unroll
            for (int i = 0; i < 32; i++) p = fmaf(k[i], v[i], p);
            p = warp_sum(p);
            float u = __fdividef(1.0f, p + EPS_STAB);
            if (l == 0) g_u[nbase + r] = u;
#pragma unroll
            for (int i = 0; i < 32; i++) vacc[i] = fmaf(k[i], u, vacc[i]);
        }
    } else {
        const uint4* Kp = reinterpret_cast<const uint4*>(g_K + (size_t)nbase * Mm);
        uint4 q[4];
#pragma unroll
        for (int j = 0; j < 4; j++) q[j] = Kp[j*32 + l];
        for (int r = 0; r < ROWS_PER_WARP; ++r) {
            uint4 qn[4];
            if (r + 1 < ROWS_PER_WARP) {
#pragma unroll
                for (int j = 0; j < 4; j++) qn[j] = Kp[(r+1)*128 + j*32 + l];
            }
            float k[32];
#pragma unroll
            for (int j = 0; j < 4; j++) cvt8(q[j], &k[j*8]);
            float p = 0.0f;
#pragma unroll
            for (int i = 0; i < 32; i++) p = fmaf(k[i], v[i], p);
            p = warp_sum(p);
            float u = __fdividef(1.0f, p + EPS_STAB);
            if (l == 0) g_u[nbase + r] = u;
#pragma unroll
            for (int i = 0; i < 32; i++) vacc[i] = fmaf(k[i], u, vacc[i]);
#pragma unroll
            for (int j = 0; j < 4; j++) q[j] = qn[j];
        }
    }

    // block-combine the 4 warps' column partials, write this chunk's partial
    __shared__ float sm[WARPS_PER_BLK][Mm];
#pragma unroll
    for (int j = 0; j < 4; j++)
#pragma unroll
        for (int e = 0; e < 8; e++)
            sm[w][j*256 + l*8 + e] = vacc[j*8 + e];
    __syncthreads();

    const int t = threadIdx.x;               // columns t*8 .. t*8+7
    float4 r0 = make_float4(0,0,0,0), r1 = make_float4(0,0,0,0);
#pragma unroll
    for (int ww = 0; ww < WARPS_PER_BLK; ww++) {
        float4 a = *reinterpret_cast<float4*>(&sm[ww][t*8]);
        float4 d = *reinterpret_cast<float4*>(&sm[ww][t*8 + 4]);
        r0.x += a.x; r0.y += a.y; r0.z += a.z; r0.w += a.w;
        r1.x += d.x; r1.y += d.y; r1.z += d.z; r1.w += d.w;
    }
    float4* vp = reinterpret_cast<float4*>(&g_vp[par][c][b * Mm + t*8]);
    vp[0] = r0;
    vp[1] = r1;
}

// ---------------------------------------------------------------- final v
__global__ void k_comb() {
    int i = blockIdx.x * blockDim.x + threadIdx.x;
    float s = g_vp[1][0][i] + g_vp[1][1][i] + g_vp[1][2][i] + g_vp[1][3][i];
    g_v[i] = __fdividef(1.0f, s + EPS_STAB);
}

// ---------------------------------------------------------------- final out
// grid (32, Bb), 128 threads: block handles 32 rows of batch b, v in smem.
__global__ void __launch_bounds__(128) k_final(float* __restrict__ out) {
    __shared__ float sv[Mm];
    const int t = threadIdx.x;
    const int b = blockIdx.y;
    const int row0 = blockIdx.x * 32;

    float4* svp = reinterpret_cast<float4*>(sv);
    const float4* gv = reinterpret_cast<const float4*>(g_v + b * Mm);
    svp[t] = gv[t];
    svp[t + 128] = gv[t + 128];
    __syncthreads();

    const size_t base = (size_t)(b * Nn + row0) * Mm;
    const uint4* Kp = reinterpret_cast<const uint4*>(g_K + base);
    float4* op = reinterpret_cast<float4*>(out + base);

    float v0[8];
#pragma unroll
    for (int e = 0; e < 8; e++) v0[e] = sv[t*8 + e];

    for (int r = 0; r < 32; ++r) {
        float u = g_u[b * Nn + row0 + r];
        uint4 q = Kp[r*128 + t];
        float k[8];
        cvt8(q, k);
        float4 o0, o1;
        o0.x = u * k[0] * v0[0]; o0.y = u * k[1] * v0[1];
        o0.z = u * k[2] * v0[2]; o0.w = u * k[3] * v0[3];
        o1.x = u * k[4] * v0[4]; o1.y = u * k[5] * v0[5];
        o1.z = u * k[6] * v0[6]; o1.w = u * k[7] * v0[7];
        op[r*256 + t*2]     = o0;
        op[r*256 + t*2 + 1] = o1;
    }
}

// ---------------------------------------------------------------- launch
extern "C" void kernel_launch(void* const* d_in, const int* in_sizes, int n_in,
                              void* d_out, int out_size) {
    const float* C = (const float*)d_in[0];
    float* out = (float*)d_out;

    k_iter<true><<<dim3(CHUNKS, Bb), 128>>>(C, 0);
    for (int it = 1; it < 10; ++it)
        k_iter<false><<<dim3(CHUNKS, Bb), 128>>>(C, it & 1);
    k_comb<<<(Bb * Mm) / 256, 256>>>();
    k_final<<<dim3(32, Bb), 128>>>(out);
}